// round 1
// baseline (speedup 1.0000x reference)
#include <cuda_runtime.h>
#include <math.h>

#define BATCH  4
#define SEQ    2048
#define DMODEL 1024
#define NHEAD  16
#define DHEAD  64
#define MROWS  (BATCH*SEQ)   // 8192

// Scratch: Q,K,V in [b,h,s,dh]; attention output in [b,s,d] (row-major 8192x1024)
__device__ float g_Q [BATCH*NHEAD*SEQ*DHEAD];
__device__ float g_K [BATCH*NHEAD*SEQ*DHEAD];
__device__ float g_V [BATCH*NHEAD*SEQ*DHEAD];
__device__ float g_AO[(size_t)MROWS*DMODEL];

// ---------------------------------------------------------------------------
// SGEMM with bias: C = A(MxK) @ W(KxN) + bias
// REMAP=1: scatter output into [b, h, s, dh] layout (for Q/K/V projections)
// REMAP=0: plain row-major [M, N] (final output projection)
// 128x128 tile, BK=8, 256 threads, 8x8 per-thread fragment.
// ---------------------------------------------------------------------------
template<int REMAP>
__global__ __launch_bounds__(256) void sgemm_bias(
    const float* __restrict__ A, const float* __restrict__ W,
    const float* __restrict__ bias, float* __restrict__ C,
    int M, int N, int K)
{
    __shared__ float As[8][128];
    __shared__ float Bs[8][128];

    const int tid = threadIdx.x;
    const int tx = tid & 15, ty = tid >> 4;
    const int m0 = blockIdx.y * 128, n0 = blockIdx.x * 128;

    float acc[8][8];
#pragma unroll
    for (int i = 0; i < 8; i++)
#pragma unroll
        for (int j = 0; j < 8; j++) acc[i][j] = 0.f;

    const int arow = tid >> 1,  ac4 = (tid & 1) * 4;   // 128 rows x 2 float4
    const int brow = tid >> 5,  bc4 = (tid & 31) * 4;  // 8 rows x 32 float4

    const float* Aptr = A + (size_t)(m0 + arow) * K + ac4;
    const float* Wptr = W + (size_t)brow * N + n0 + bc4;

    for (int kt = 0; kt < K; kt += 8) {
        float4 av = *reinterpret_cast<const float4*>(Aptr + kt);
        As[ac4+0][arow] = av.x;
        As[ac4+1][arow] = av.y;
        As[ac4+2][arow] = av.z;
        As[ac4+3][arow] = av.w;
        float4 bv4 = *reinterpret_cast<const float4*>(Wptr + (size_t)kt * N);
        *reinterpret_cast<float4*>(&Bs[brow][bc4]) = bv4;
        __syncthreads();

#pragma unroll
        for (int k = 0; k < 8; k++) {
            float a[8], b[8];
#pragma unroll
            for (int i = 0; i < 8; i++) a[i] = As[k][ty*8+i];
#pragma unroll
            for (int j = 0; j < 8; j++) b[j] = Bs[k][tx*8+j];
#pragma unroll
            for (int i = 0; i < 8; i++)
#pragma unroll
                for (int j = 0; j < 8; j++)
                    acc[i][j] = fmaf(a[i], b[j], acc[i][j]);
        }
        __syncthreads();
    }

    float bv[8];
#pragma unroll
    for (int j = 0; j < 8; j++) bv[j] = bias[n0 + tx*8 + j];

#pragma unroll
    for (int i = 0; i < 8; i++) {
        const int m = m0 + ty*8 + i;
        const int n = n0 + tx*8;
        if (REMAP) {
            // m = bb*SEQ + ss ; n = hh*DHEAD + dd ; out[b][h][s][dh]
            const int bb = m >> 11;          // / 2048
            const int ss = m & 2047;
            const int hh = n >> 6;           // / 64  (8 cols stay in one head)
            const int dd = n & 63;
            float* out = C + (((size_t)(bb*NHEAD + hh)*SEQ + ss)*DHEAD + dd);
#pragma unroll
            for (int j = 0; j < 8; j++) out[j] = acc[i][j] + bv[j];
        } else {
            float* out = C + (size_t)m * N + n;
#pragma unroll
            for (int j = 0; j < 8; j++) out[j] = acc[i][j] + bv[j];
        }
    }
}

// ---------------------------------------------------------------------------
// Flash attention: one block per (q-tile of 64, head, batch).
// Online softmax over 64-wide K/V tiles; causal tiles beyond the diagonal
// are skipped entirely (halves the work). 256 threads, 4x4 fragments.
// Output written to [b, s, h*dh] so the O-projection GEMM is plain row-major.
// ---------------------------------------------------------------------------
__global__ __launch_bounds__(256) void flash_attn(
    const float* __restrict__ Q, const float* __restrict__ K,
    const float* __restrict__ V, float* __restrict__ AO,
    const int* __restrict__ maskp)
{
    extern __shared__ float sm[];
    float (*Qs)[65] = (float(*)[65])(sm);
    float (*Ks)[65] = (float(*)[65])(sm + 64*65);
    float (*Vs)[65] = (float(*)[65])(sm + 2*64*65);
    float (*Ps)[65] = (float(*)[65])(sm + 3*64*65);

    const int tid = threadIdx.x;
    const int tx = tid & 15, ty = tid >> 4;
    const int qt = blockIdx.x, hh = blockIdx.y, bb = blockIdx.z;
    const int q0 = qt * 64;
    const size_t bh = ((size_t)bb*NHEAD + hh) * SEQ * DHEAD;
    const int causal = (maskp[0] != 0);   // nonzero bits => causal (robust to int/float 1)

    // Load Q tile (64x64) into shared (padded rows)
    const float* Qg = Q + bh + (size_t)q0 * DHEAD;
#pragma unroll
    for (int i = 0; i < 4; i++) {
        const int lin = tid + i*256;           // float4 index 0..1023
        const int r = lin >> 4, c4 = (lin & 15) * 4;
        float4 v = *reinterpret_cast<const float4*>(Qg + r*DHEAD + c4);
        Qs[r][c4+0]=v.x; Qs[r][c4+1]=v.y; Qs[r][c4+2]=v.z; Qs[r][c4+3]=v.w;
    }

    float m_i[4], l_i[4], O[4][4];
#pragma unroll
    for (int i = 0; i < 4; i++) {
        m_i[i] = -INFINITY; l_i[i] = 0.f;
#pragma unroll
        for (int j = 0; j < 4; j++) O[i][j] = 0.f;
    }

    const int ktmax = causal ? qt : (SEQ/64 - 1);
    for (int kt = 0; kt <= ktmax; kt++) {
        const float* Kg = K + bh + (size_t)kt*64*DHEAD;
        const float* Vg = V + bh + (size_t)kt*64*DHEAD;
        __syncthreads();   // prior iter done reading Ks/Vs/Ps; Qs ready (1st iter)
#pragma unroll
        for (int i = 0; i < 4; i++) {
            const int lin = tid + i*256;
            const int r = lin >> 4, c4 = (lin & 15) * 4;
            float4 kv = *reinterpret_cast<const float4*>(Kg + r*DHEAD + c4);
            Ks[r][c4+0]=kv.x; Ks[r][c4+1]=kv.y; Ks[r][c4+2]=kv.z; Ks[r][c4+3]=kv.w;
            float4 vv = *reinterpret_cast<const float4*>(Vg + r*DHEAD + c4);
            Vs[r][c4+0]=vv.x; Vs[r][c4+1]=vv.y; Vs[r][c4+2]=vv.z; Vs[r][c4+3]=vv.w;
        }
        __syncthreads();

        // S = Q @ K^T (64x64), 4x4 fragment per thread
        float Sf[4][4];
#pragma unroll
        for (int i = 0; i < 4; i++)
#pragma unroll
            for (int j = 0; j < 4; j++) Sf[i][j] = 0.f;
#pragma unroll
        for (int d = 0; d < 64; d++) {
            float a[4], b[4];
#pragma unroll
            for (int i = 0; i < 4; i++) a[i] = Qs[ty*4+i][d];
#pragma unroll
            for (int j = 0; j < 4; j++) b[j] = Ks[tx*4+j][d];
#pragma unroll
            for (int i = 0; i < 4; i++)
#pragma unroll
                for (int j = 0; j < 4; j++)
                    Sf[i][j] = fmaf(a[i], b[j], Sf[i][j]);
        }

        // scale 1/sqrt(dh) = 0.125, causal mask only on the diagonal tile
        const bool diag = causal && (kt == qt);
#pragma unroll
        for (int i = 0; i < 4; i++)
#pragma unroll
            for (int j = 0; j < 4; j++) {
                float s = Sf[i][j] * 0.125f;
                if (diag) {
                    const int q = q0 + ty*4 + i;
                    const int k = kt*64 + tx*4 + j;
                    if (k > q) s = -INFINITY;
                }
                Sf[i][j] = s;
            }

        // online softmax: row reductions across the 16 tx lanes (same half-warp)
#pragma unroll
        for (int i = 0; i < 4; i++) {
            float rmax = fmaxf(fmaxf(Sf[i][0], Sf[i][1]), fmaxf(Sf[i][2], Sf[i][3]));
#pragma unroll
            for (int off = 1; off < 16; off <<= 1)
                rmax = fmaxf(rmax, __shfl_xor_sync(0xffffffffu, rmax, off));
            const float mnew = fmaxf(m_i[i], rmax);
            const float corr = __expf(m_i[i] - mnew);
            m_i[i] = mnew;
            float rsum = 0.f;
#pragma unroll
            for (int j = 0; j < 4; j++) {
                const float p = __expf(Sf[i][j] - mnew);
                Sf[i][j] = p;
                rsum += p;
            }
#pragma unroll
            for (int off = 1; off < 16; off <<= 1)
                rsum += __shfl_xor_sync(0xffffffffu, rsum, off);
            l_i[i] = l_i[i]*corr + rsum;
#pragma unroll
            for (int j = 0; j < 4; j++) O[i][j] *= corr;
        }

        // stage P, then O += P @ V
#pragma unroll
        for (int i = 0; i < 4; i++)
#pragma unroll
            for (int j = 0; j < 4; j++) Ps[ty*4+i][tx*4+j] = Sf[i][j];
        __syncthreads();
#pragma unroll
        for (int k = 0; k < 64; k++) {
            float a[4], b[4];
#pragma unroll
            for (int i = 0; i < 4; i++) a[i] = Ps[ty*4+i][k];
#pragma unroll
            for (int j = 0; j < 4; j++) b[j] = Vs[k][tx*4+j];
#pragma unroll
            for (int i = 0; i < 4; i++)
#pragma unroll
                for (int j = 0; j < 4; j++)
                    O[i][j] = fmaf(a[i], b[j], O[i][j]);
        }
    }

    // normalize and write to [b, s, h*dh]
#pragma unroll
    for (int i = 0; i < 4; i++) {
        const int q = q0 + ty*4 + i;
        const float inv = 1.f / l_i[i];
        float* out = AO + ((size_t)bb*SEQ + q)*DMODEL + hh*DHEAD + tx*4;
#pragma unroll
        for (int j = 0; j < 4; j++) out[j] = O[i][j] * inv;
    }
}

// ---------------------------------------------------------------------------
extern "C" void kernel_launch(void* const* d_in, const int* in_sizes, int n_in,
                              void* d_out, int out_size)
{
    const float* x    = (const float*)d_in[0];
    const float* Wq   = (const float*)d_in[1];
    const float* bq   = (const float*)d_in[2];
    const float* Wk   = (const float*)d_in[3];
    const float* bk   = (const float*)d_in[4];
    const float* Wv   = (const float*)d_in[5];
    const float* bv   = (const float*)d_in[6];
    const float* Wo   = (const float*)d_in[7];
    const float* bo   = (const float*)d_in[8];
    const int*   mask = (const int*)  d_in[9];
    float* out = (float*)d_out;

    float *Qp, *Kp, *Vp, *AOp;
    cudaGetSymbolAddress((void**)&Qp,  g_Q);
    cudaGetSymbolAddress((void**)&Kp,  g_K);
    cudaGetSymbolAddress((void**)&Vp,  g_V);
    cudaGetSymbolAddress((void**)&AOp, g_AO);

    const int smem_attn = 4 * 64 * 65 * (int)sizeof(float);  // 66560 B
    cudaFuncSetAttribute(flash_attn, cudaFuncAttributeMaxDynamicSharedMemorySize,
                         smem_attn);

    dim3 gproj(DMODEL/128, MROWS/128);   // (8, 64)
    sgemm_bias<1><<<gproj, 256>>>(x, Wq, bq, Qp, MROWS, DMODEL, DMODEL);
    sgemm_bias<1><<<gproj, 256>>>(x, Wk, bk, Kp, MROWS, DMODEL, DMODEL);
    sgemm_bias<1><<<gproj, 256>>>(x, Wv, bv, Vp, MROWS, DMODEL, DMODEL);

    dim3 gattn(SEQ/64, NHEAD, BATCH);    // (32, 16, 4)
    flash_attn<<<gattn, 256, smem_attn>>>(Qp, Kp, Vp, AOp, mask);

    sgemm_bias<0><<<gproj, 256>>>(AOp, Wo, bo, out, MROWS, DMODEL, DMODEL);
}

// round 3
// speedup vs baseline: 1.7538x; 1.7538x over previous
#include <cuda_runtime.h>
#include <math.h>
#include <stdint.h>

#define BATCH  4
#define SEQ    2048
#define DMODEL 1024
#define NHEAD  16
#define DHEAD  64
#define MROWS  (BATCH*SEQ)   // 8192

// Scratch
__device__ float g_Q [BATCH*NHEAD*SEQ*DHEAD];
__device__ float g_K [BATCH*NHEAD*SEQ*DHEAD];
__device__ float g_V [BATCH*NHEAD*SEQ*DHEAD];
__device__ float g_AO[(size_t)MROWS*DMODEL];

// ---------------------------------------------------------------------------
__device__ __forceinline__ uint32_t f2tf32(float f) {
    uint32_t u;
    asm("cvt.rna.tf32.f32 %0, %1;" : "=r"(u) : "f"(f));
    return u;
}
__device__ __forceinline__ void mma_tf32(float* d, const uint32_t* a,
                                         const uint32_t* b) {
    asm volatile(
        "mma.sync.aligned.m16n8k8.row.col.f32.tf32.tf32.f32 "
        "{%0,%1,%2,%3}, {%4,%5,%6,%7}, {%8,%9}, {%0,%1,%2,%3};"
        : "+f"(d[0]), "+f"(d[1]), "+f"(d[2]), "+f"(d[3])
        : "r"(a[0]), "r"(a[1]), "r"(a[2]), "r"(a[3]),
          "r"(b[0]), "r"(b[1]));
}

// ---------------------------------------------------------------------------
// tf32 tensor-core GEMM: C[8192,1024] = A[8192,1024] @ W[1024,1024] + bias
// CTA 128x128, BK=16, 8 warps (2x4), warp tile 64x32, double-buffered SMEM
// with register prefetch. REMAP=1 scatters C into [b, h, s, dh].
// SMEM pitches: A [m][k] pitch 20 (conflict-free A-frag lds),
//               B [k][n] pitch 136 (conflict-free B-frag lds).
// ---------------------------------------------------------------------------
#define APITCH 20
#define BPITCH 136

template<int REMAP>
__global__ __launch_bounds__(256) void gemm_mma(
    const float* __restrict__ A, const float* __restrict__ W,
    const float* __restrict__ bias, float* __restrict__ C)
{
    __shared__ uint32_t As[2][128 * APITCH];   // 2 x 10240 B
    __shared__ uint32_t Bs[2][16  * BPITCH];   // 2 x  8704 B

    const int tid  = threadIdx.x;
    const int wid  = tid >> 5, lane = tid & 31;
    const int g    = lane >> 2, t = lane & 3;
    const int m0   = blockIdx.y * 128, n0 = blockIdx.x * 128;
    const int wm0  = (wid >> 2) * 64, wn0 = (wid & 3) * 32;

    // loader indices: 512 float4 per tile over 256 threads (2 each)
    const int am[2] = { (tid + 0)   >> 2, (tid + 256) >> 2 };
    const int ak[2] = { ((tid + 0)  & 3) << 2, ((tid + 256) & 3) << 2 };
    const int bk[2] = { (tid + 0)   >> 5, (tid + 256) >> 5 };
    const int bn[2] = { ((tid + 0)  & 31) << 2, ((tid + 256) & 31) << 2 };

    float4 pa[2], pb[2];

    auto loadg = [&](int kt) {
#pragma unroll
        for (int i = 0; i < 2; i++) {
            pa[i] = *reinterpret_cast<const float4*>(
                A + (size_t)(m0 + am[i]) * DMODEL + kt * 16 + ak[i]);
            pb[i] = *reinterpret_cast<const float4*>(
                W + (size_t)(kt * 16 + bk[i]) * DMODEL + n0 + bn[i]);
        }
    };
    auto stores = [&](int s) {
#pragma unroll
        for (int i = 0; i < 2; i++) {
            uint32_t* pA = &As[s][am[i] * APITCH + ak[i]];
            pA[0] = f2tf32(pa[i].x); pA[1] = f2tf32(pa[i].y);
            pA[2] = f2tf32(pa[i].z); pA[3] = f2tf32(pa[i].w);
            uint32_t* pB = &Bs[s][bk[i] * BPITCH + bn[i]];
            pB[0] = f2tf32(pb[i].x); pB[1] = f2tf32(pb[i].y);
            pB[2] = f2tf32(pb[i].z); pB[3] = f2tf32(pb[i].w);
        }
    };

    float acc[4][4][4];
#pragma unroll
    for (int mt = 0; mt < 4; mt++)
#pragma unroll
        for (int nt = 0; nt < 4; nt++)
#pragma unroll
            for (int r = 0; r < 4; r++) acc[mt][nt][r] = 0.f;

    loadg(0);
    stores(0);
    __syncthreads();

    const int NKT = DMODEL / 16;   // 64
    for (int kt = 0; kt < NKT; kt++) {
        const int s = kt & 1;
        if (kt < NKT - 1) loadg(kt + 1);

#pragma unroll
        for (int ks = 0; ks < 2; ks++) {
            const int k0 = ks * 8;
            uint32_t af[4][4], bf[4][2];
#pragma unroll
            for (int mt = 0; mt < 4; mt++) {
                const int rb = wm0 + mt * 16;
                af[mt][0] = As[s][(rb + g)     * APITCH + k0 + t];
                af[mt][1] = As[s][(rb + g + 8) * APITCH + k0 + t];
                af[mt][2] = As[s][(rb + g)     * APITCH + k0 + t + 4];
                af[mt][3] = As[s][(rb + g + 8) * APITCH + k0 + t + 4];
            }
#pragma unroll
            for (int nt = 0; nt < 4; nt++) {
                const int col = wn0 + nt * 8 + g;
                bf[nt][0] = Bs[s][(k0 + t)     * BPITCH + col];
                bf[nt][1] = Bs[s][(k0 + t + 4) * BPITCH + col];
            }
#pragma unroll
            for (int mt = 0; mt < 4; mt++)
#pragma unroll
                for (int nt = 0; nt < 4; nt++)
                    mma_tf32(acc[mt][nt], af[mt], bf[nt]);
        }

        if (kt < NKT - 1) stores(s ^ 1);
        __syncthreads();
    }

    // epilogue: c0 at (g, t*2), c1 (g, t*2+1), c2/c3 at row g+8
#pragma unroll
    for (int mt = 0; mt < 4; mt++) {
#pragma unroll
        for (int nt = 0; nt < 4; nt++) {
            const int row = m0 + wm0 + mt * 16 + g;
            const int col = n0 + wn0 + nt * 8 + t * 2;
            const float b0 = bias[col], b1 = bias[col + 1];
#pragma unroll
            for (int half = 0; half < 2; half++) {
                const int m = row + half * 8;
                float2 v = make_float2(acc[mt][nt][half*2]   + b0,
                                       acc[mt][nt][half*2+1] + b1);
                float* outp;
                if (REMAP) {
                    const int bb = m >> 11, ss = m & 2047;
                    const int hh = col >> 6, dd = col & 63;
                    outp = C + (((size_t)(bb * NHEAD + hh) * SEQ + ss) * DHEAD + dd);
                } else {
                    outp = C + (size_t)m * DMODEL + col;
                }
                *reinterpret_cast<float2*>(outp) = v;
            }
        }
    }
}

// ---------------------------------------------------------------------------
// Flash attention (unchanged, passing): fp32 FFMA, 64x64 tiles, causal skip
// ---------------------------------------------------------------------------
__global__ __launch_bounds__(256) void flash_attn(
    const float* __restrict__ Q, const float* __restrict__ K,
    const float* __restrict__ V, float* __restrict__ AO,
    const int* __restrict__ maskp)
{
    extern __shared__ float sm[];
    float (*Qs)[65] = (float(*)[65])(sm);
    float (*Ks)[65] = (float(*)[65])(sm + 64*65);
    float (*Vs)[65] = (float(*)[65])(sm + 2*64*65);
    float (*Ps)[65] = (float(*)[65])(sm + 3*64*65);

    const int tid = threadIdx.x;
    const int tx = tid & 15, ty = tid >> 4;
    const int qt = blockIdx.x, hh = blockIdx.y, bb = blockIdx.z;
    const int q0 = qt * 64;
    const size_t bh = ((size_t)bb*NHEAD + hh) * SEQ * DHEAD;
    const int causal = (maskp[0] != 0);

    const float* Qg = Q + bh + (size_t)q0 * DHEAD;
#pragma unroll
    for (int i = 0; i < 4; i++) {
        const int lin = tid + i*256;
        const int r = lin >> 4, c4 = (lin & 15) * 4;
        float4 v = *reinterpret_cast<const float4*>(Qg + r*DHEAD + c4);
        Qs[r][c4+0]=v.x; Qs[r][c4+1]=v.y; Qs[r][c4+2]=v.z; Qs[r][c4+3]=v.w;
    }

    float m_i[4], l_i[4], O[4][4];
#pragma unroll
    for (int i = 0; i < 4; i++) {
        m_i[i] = -INFINITY; l_i[i] = 0.f;
#pragma unroll
        for (int j = 0; j < 4; j++) O[i][j] = 0.f;
    }

    const int ktmax = causal ? qt : (SEQ/64 - 1);
    for (int kt = 0; kt <= ktmax; kt++) {
        const float* Kg = K + bh + (size_t)kt*64*DHEAD;
        const float* Vg = V + bh + (size_t)kt*64*DHEAD;
        __syncthreads();
#pragma unroll
        for (int i = 0; i < 4; i++) {
            const int lin = tid + i*256;
            const int r = lin >> 4, c4 = (lin & 15) * 4;
            float4 kv = *reinterpret_cast<const float4*>(Kg + r*DHEAD + c4);
            Ks[r][c4+0]=kv.x; Ks[r][c4+1]=kv.y; Ks[r][c4+2]=kv.z; Ks[r][c4+3]=kv.w;
            float4 vv = *reinterpret_cast<const float4*>(Vg + r*DHEAD + c4);
            Vs[r][c4+0]=vv.x; Vs[r][c4+1]=vv.y; Vs[r][c4+2]=vv.z; Vs[r][c4+3]=vv.w;
        }
        __syncthreads();

        float Sf[4][4];
#pragma unroll
        for (int i = 0; i < 4; i++)
#pragma unroll
            for (int j = 0; j < 4; j++) Sf[i][j] = 0.f;
#pragma unroll
        for (int d = 0; d < 64; d++) {
            float a[4], b[4];
#pragma unroll
            for (int i = 0; i < 4; i++) a[i] = Qs[ty*4+i][d];
#pragma unroll
            for (int j = 0; j < 4; j++) b[j] = Ks[tx*4+j][d];
#pragma unroll
            for (int i = 0; i < 4; i++)
#pragma unroll
                for (int j = 0; j < 4; j++)
                    Sf[i][j] = fmaf(a[i], b[j], Sf[i][j]);
        }

        const bool diag = causal && (kt == qt);
#pragma unroll
        for (int i = 0; i < 4; i++)
#pragma unroll
            for (int j = 0; j < 4; j++) {
                float s = Sf[i][j] * 0.125f;
                if (diag) {
                    const int q = q0 + ty*4 + i;
                    const int k = kt*64 + tx*4 + j;
                    if (k > q) s = -INFINITY;
                }
                Sf[i][j] = s;
            }

#pragma unroll
        for (int i = 0; i < 4; i++) {
            float rmax = fmaxf(fmaxf(Sf[i][0], Sf[i][1]), fmaxf(Sf[i][2], Sf[i][3]));
#pragma unroll
            for (int off = 1; off < 16; off <<= 1)
                rmax = fmaxf(rmax, __shfl_xor_sync(0xffffffffu, rmax, off));
            const float mnew = fmaxf(m_i[i], rmax);
            const float corr = __expf(m_i[i] - mnew);
            m_i[i] = mnew;
            float rsum = 0.f;
#pragma unroll
            for (int j = 0; j < 4; j++) {
                const float p = __expf(Sf[i][j] - mnew);
                Sf[i][j] = p;
                rsum += p;
            }
#pragma unroll
            for (int off = 1; off < 16; off <<= 1)
                rsum += __shfl_xor_sync(0xffffffffu, rsum, off);
            l_i[i] = l_i[i]*corr + rsum;
#pragma unroll
            for (int j = 0; j < 4; j++) O[i][j] *= corr;
        }

#pragma unroll
        for (int i = 0; i < 4; i++)
#pragma unroll
            for (int j = 0; j < 4; j++) Ps[ty*4+i][tx*4+j] = Sf[i][j];
        __syncthreads();
#pragma unroll
        for (int k = 0; k < 64; k++) {
            float a[4], b[4];
#pragma unroll
            for (int i = 0; i < 4; i++) a[i] = Ps[ty*4+i][k];
#pragma unroll
            for (int j = 0; j < 4; j++) b[j] = Vs[k][tx*4+j];
#pragma unroll
            for (int i = 0; i < 4; i++)
#pragma unroll
                for (int j = 0; j < 4; j++)
                    O[i][j] = fmaf(a[i], b[j], O[i][j]);
        }
    }

#pragma unroll
    for (int i = 0; i < 4; i++) {
        const int q = q0 + ty*4 + i;
        const float inv = 1.f / l_i[i];
        float* out = AO + ((size_t)bb*SEQ + q)*DMODEL + hh*DHEAD + tx*4;
#pragma unroll
        for (int j = 0; j < 4; j++) out[j] = O[i][j] * inv;
    }
}

// ---------------------------------------------------------------------------
extern "C" void kernel_launch(void* const* d_in, const int* in_sizes, int n_in,
                              void* d_out, int out_size)
{
    const float* x    = (const float*)d_in[0];
    const float* Wq   = (const float*)d_in[1];
    const float* bq   = (const float*)d_in[2];
    const float* Wk   = (const float*)d_in[3];
    const float* bk   = (const float*)d_in[4];
    const float* Wv   = (const float*)d_in[5];
    const float* bv   = (const float*)d_in[6];
    const float* Wo   = (const float*)d_in[7];
    const float* bo   = (const float*)d_in[8];
    const int*   mask = (const int*)  d_in[9];
    float* out = (float*)d_out;

    float *Qp, *Kp, *Vp, *AOp;
    cudaGetSymbolAddress((void**)&Qp,  g_Q);
    cudaGetSymbolAddress((void**)&Kp,  g_K);
    cudaGetSymbolAddress((void**)&Vp,  g_V);
    cudaGetSymbolAddress((void**)&AOp, g_AO);

    const int smem_attn = 4 * 64 * 65 * (int)sizeof(float);
    cudaFuncSetAttribute(flash_attn, cudaFuncAttributeMaxDynamicSharedMemorySize,
                         smem_attn);

    dim3 gg(DMODEL/128, MROWS/128);   // (8, 64)
    gemm_mma<1><<<gg, 256>>>(x, Wq, bq, Qp);
    gemm_mma<1><<<gg, 256>>>(x, Wk, bk, Kp);
    gemm_mma<1><<<gg, 256>>>(x, Wv, bv, Vp);

    dim3 gattn(SEQ/64, NHEAD, BATCH);
    flash_attn<<<gattn, 256, smem_attn>>>(Qp, Kp, Vp, AOp, mask);

    gemm_mma<0><<<gg, 256>>>(AOp, Wo, bo, out);
}

// round 4
// speedup vs baseline: 3.0909x; 1.7624x over previous
#include <cuda_runtime.h>
#include <math.h>
#include <stdint.h>

#define BATCH  4
#define SEQ    2048
#define DMODEL 1024
#define NHEAD  16
#define DHEAD  64
#define MROWS  (BATCH*SEQ)   // 8192

// Scratch
__device__ float g_Q [BATCH*NHEAD*SEQ*DHEAD];
__device__ float g_K [BATCH*NHEAD*SEQ*DHEAD];
__device__ float g_V [BATCH*NHEAD*SEQ*DHEAD];
__device__ float g_AO[(size_t)MROWS*DMODEL];

// ---------------------------------------------------------------------------
__device__ __forceinline__ uint32_t f2tf32(float f) {
    uint32_t u;
    asm("cvt.rna.tf32.f32 %0, %1;" : "=r"(u) : "f"(f));
    return u;
}
__device__ __forceinline__ void mma_tf32(float* d, const uint32_t* a,
                                         const uint32_t* b) {
    asm volatile(
        "mma.sync.aligned.m16n8k8.row.col.f32.tf32.tf32.f32 "
        "{%0,%1,%2,%3}, {%4,%5,%6,%7}, {%8,%9}, {%0,%1,%2,%3};"
        : "+f"(d[0]), "+f"(d[1]), "+f"(d[2]), "+f"(d[3])
        : "r"(a[0]), "r"(a[1]), "r"(a[2]), "r"(a[3]),
          "r"(b[0]), "r"(b[1]));
}

// ---------------------------------------------------------------------------
// tf32 tensor-core GEMM (unchanged from round 3, passing)
// ---------------------------------------------------------------------------
#define APITCH 20
#define BPITCH 136

template<int REMAP>
__global__ __launch_bounds__(256) void gemm_mma(
    const float* __restrict__ A, const float* __restrict__ W,
    const float* __restrict__ bias, float* __restrict__ C)
{
    __shared__ uint32_t As[2][128 * APITCH];
    __shared__ uint32_t Bs[2][16  * BPITCH];

    const int tid  = threadIdx.x;
    const int wid  = tid >> 5, lane = tid & 31;
    const int g    = lane >> 2, t = lane & 3;
    const int m0   = blockIdx.y * 128, n0 = blockIdx.x * 128;
    const int wm0  = (wid >> 2) * 64, wn0 = (wid & 3) * 32;

    const int am[2] = { (tid + 0)   >> 2, (tid + 256) >> 2 };
    const int ak[2] = { ((tid + 0)  & 3) << 2, ((tid + 256) & 3) << 2 };
    const int bk[2] = { (tid + 0)   >> 5, (tid + 256) >> 5 };
    const int bn[2] = { ((tid + 0)  & 31) << 2, ((tid + 256) & 31) << 2 };

    float4 pa[2], pb[2];

    auto loadg = [&](int kt) {
#pragma unroll
        for (int i = 0; i < 2; i++) {
            pa[i] = *reinterpret_cast<const float4*>(
                A + (size_t)(m0 + am[i]) * DMODEL + kt * 16 + ak[i]);
            pb[i] = *reinterpret_cast<const float4*>(
                W + (size_t)(kt * 16 + bk[i]) * DMODEL + n0 + bn[i]);
        }
    };
    auto stores = [&](int s) {
#pragma unroll
        for (int i = 0; i < 2; i++) {
            uint32_t* pA = &As[s][am[i] * APITCH + ak[i]];
            pA[0] = f2tf32(pa[i].x); pA[1] = f2tf32(pa[i].y);
            pA[2] = f2tf32(pa[i].z); pA[3] = f2tf32(pa[i].w);
            uint32_t* pB = &Bs[s][bk[i] * BPITCH + bn[i]];
            pB[0] = f2tf32(pb[i].x); pB[1] = f2tf32(pb[i].y);
            pB[2] = f2tf32(pb[i].z); pB[3] = f2tf32(pb[i].w);
        }
    };

    float acc[4][4][4];
#pragma unroll
    for (int mt = 0; mt < 4; mt++)
#pragma unroll
        for (int nt = 0; nt < 4; nt++)
#pragma unroll
            for (int r = 0; r < 4; r++) acc[mt][nt][r] = 0.f;

    loadg(0);
    stores(0);
    __syncthreads();

    const int NKT = DMODEL / 16;
    for (int kt = 0; kt < NKT; kt++) {
        const int s = kt & 1;
        if (kt < NKT - 1) loadg(kt + 1);

#pragma unroll
        for (int ks = 0; ks < 2; ks++) {
            const int k0 = ks * 8;
            uint32_t af[4][4], bf[4][2];
#pragma unroll
            for (int mt = 0; mt < 4; mt++) {
                const int rb = wm0 + mt * 16;
                af[mt][0] = As[s][(rb + g)     * APITCH + k0 + t];
                af[mt][1] = As[s][(rb + g + 8) * APITCH + k0 + t];
                af[mt][2] = As[s][(rb + g)     * APITCH + k0 + t + 4];
                af[mt][3] = As[s][(rb + g + 8) * APITCH + k0 + t + 4];
            }
#pragma unroll
            for (int nt = 0; nt < 4; nt++) {
                const int col = wn0 + nt * 8 + g;
                bf[nt][0] = Bs[s][(k0 + t)     * BPITCH + col];
                bf[nt][1] = Bs[s][(k0 + t + 4) * BPITCH + col];
            }
#pragma unroll
            for (int mt = 0; mt < 4; mt++)
#pragma unroll
                for (int nt = 0; nt < 4; nt++)
                    mma_tf32(acc[mt][nt], af[mt], bf[nt]);
        }

        if (kt < NKT - 1) stores(s ^ 1);
        __syncthreads();
    }

#pragma unroll
    for (int mt = 0; mt < 4; mt++) {
#pragma unroll
        for (int nt = 0; nt < 4; nt++) {
            const int row = m0 + wm0 + mt * 16 + g;
            const int col = n0 + wn0 + nt * 8 + t * 2;
            const float b0 = bias[col], b1 = bias[col + 1];
#pragma unroll
            for (int half = 0; half < 2; half++) {
                const int m = row + half * 8;
                float2 v = make_float2(acc[mt][nt][half*2]   + b0,
                                       acc[mt][nt][half*2+1] + b1);
                float* outp;
                if (REMAP) {
                    const int bb = m >> 11, ss = m & 2047;
                    const int hh = col >> 6, dd = col & 63;
                    outp = C + (((size_t)(bb * NHEAD + hh) * SEQ + ss) * DHEAD + dd);
                } else {
                    outp = C + (size_t)m * DMODEL + col;
                }
                *reinterpret_cast<float2*>(outp) = v;
            }
        }
    }
}

// ---------------------------------------------------------------------------
// Flash attention on tensor cores (tf32 mma.sync).
// CTA = 128 threads (4 warps), q-tile 64, kv-tile 64. Warp w owns q-rows
// [w*16, w*16+16). S = Q@K^T and O += P@V via m16n8k8.
// SMEM word pitches: Qs/Ks/Ps = 68 (bank 4g+t bijective), Vs = 72 (8t+g).
// ---------------------------------------------------------------------------
#define QP 68
#define VP 72
#define QS_OFF 0
#define KS_OFF 4352
#define VS_OFF 8704
#define PS_OFF 13312
#define FA_SMEM_WORDS (PS_OFF + 4352)   // 17664 words = 70656 B

__global__ __launch_bounds__(128) void flash_attn_mma(
    const float* __restrict__ Q, const float* __restrict__ K,
    const float* __restrict__ V, float* __restrict__ AO,
    const int* __restrict__ maskp)
{
    extern __shared__ uint32_t su[];
    uint32_t* Qs = su + QS_OFF;
    uint32_t* Ks = su + KS_OFF;
    uint32_t* Vs = su + VS_OFF;
    uint32_t* Ps = su + PS_OFF;

    const int tid = threadIdx.x;
    const int wid = tid >> 5, lane = tid & 31;
    const int g = lane >> 2, t = lane & 3;
    const int qt = blockIdx.x, hh = blockIdx.y, bb = blockIdx.z;
    const int q0 = qt * 64;
    const int wr0 = wid * 16;
    const size_t bh = ((size_t)bb*NHEAD + hh) * SEQ * DHEAD;
    const int causal = (maskp[0] != 0);

    // Q tile -> SMEM (tf32)
    const float* Qg = Q + bh + (size_t)q0 * DHEAD;
#pragma unroll
    for (int i = 0; i < 8; i++) {
        const int lin = tid + i * 128;      // float4 index 0..1023
        const int r = lin >> 4, c = (lin & 15) * 4;
        float4 v = *reinterpret_cast<const float4*>(Qg + r*DHEAD + c);
        uint32_t* p = Qs + r*QP + c;
        p[0]=f2tf32(v.x); p[1]=f2tf32(v.y); p[2]=f2tf32(v.z); p[3]=f2tf32(v.w);
    }

    float m_i[2] = { -INFINITY, -INFINITY };
    float l_i[2] = { 0.f, 0.f };
    float accO[8][4];
#pragma unroll
    for (int nt = 0; nt < 8; nt++)
#pragma unroll
        for (int c = 0; c < 4; c++) accO[nt][c] = 0.f;

    const int ktmax = causal ? qt : (SEQ/64 - 1);
    for (int kt = 0; kt <= ktmax; kt++) {
        __syncthreads();   // prior iter's Vs/Ps reads complete
        const float* Kg = K + bh + (size_t)kt*64*DHEAD;
        const float* Vg = V + bh + (size_t)kt*64*DHEAD;
#pragma unroll
        for (int i = 0; i < 8; i++) {
            const int lin = tid + i * 128;
            const int r = lin >> 4, c = (lin & 15) * 4;
            float4 kv = *reinterpret_cast<const float4*>(Kg + r*DHEAD + c);
            uint32_t* pk = Ks + r*QP + c;
            pk[0]=f2tf32(kv.x); pk[1]=f2tf32(kv.y); pk[2]=f2tf32(kv.z); pk[3]=f2tf32(kv.w);
            float4 vv = *reinterpret_cast<const float4*>(Vg + r*DHEAD + c);
            uint32_t* pv = Vs + r*VP + c;
            pv[0]=f2tf32(vv.x); pv[1]=f2tf32(vv.y); pv[2]=f2tf32(vv.z); pv[3]=f2tf32(vv.w);
        }
        __syncthreads();

        // S = Q @ K^T : warp computes 16x64
        float accS[8][4];
#pragma unroll
        for (int nt = 0; nt < 8; nt++)
#pragma unroll
            for (int c = 0; c < 4; c++) accS[nt][c] = 0.f;
#pragma unroll
        for (int kc = 0; kc < 8; kc++) {
            uint32_t af[4];
            const uint32_t* qb = Qs + (wr0 + g)*QP + kc*8 + t;
            af[0] = qb[0]; af[1] = qb[8*QP]; af[2] = qb[4]; af[3] = qb[8*QP + 4];
#pragma unroll
            for (int nt = 0; nt < 8; nt++) {
                uint32_t bf[2];
                const uint32_t* kb = Ks + (nt*8 + g)*QP + kc*8 + t;
                bf[0] = kb[0]; bf[1] = kb[4];
                mma_tf32(accS[nt], af, bf);
            }
        }

        // scale + causal mask (diag tile only)
        const bool diag = causal && (kt == qt);
#pragma unroll
        for (int nt = 0; nt < 8; nt++)
#pragma unroll
            for (int c = 0; c < 4; c++) {
                float s = accS[nt][c] * 0.125f;
                if (diag) {
                    const int grow = q0 + wr0 + g + ((c & 2) ? 8 : 0);
                    const int gcol = kt*64 + nt*8 + 2*t + (c & 1);
                    if (gcol > grow) s = -INFINITY;
                }
                accS[nt][c] = s;
            }

        // online softmax per row-half r (r=0: row g, r=1: row g+8)
#pragma unroll
        for (int r = 0; r < 2; r++) {
            float rmax = -INFINITY;
#pragma unroll
            for (int nt = 0; nt < 8; nt++)
                rmax = fmaxf(rmax, fmaxf(accS[nt][2*r], accS[nt][2*r+1]));
            rmax = fmaxf(rmax, __shfl_xor_sync(0xffffffffu, rmax, 1));
            rmax = fmaxf(rmax, __shfl_xor_sync(0xffffffffu, rmax, 2));
            const float mnew = fmaxf(m_i[r], rmax);
            const float corr = __expf(m_i[r] - mnew);
            m_i[r] = mnew;
            float rsum = 0.f;
#pragma unroll
            for (int nt = 0; nt < 8; nt++) {
                const float p0 = __expf(accS[nt][2*r]   - mnew);
                const float p1 = __expf(accS[nt][2*r+1] - mnew);
                accS[nt][2*r] = p0; accS[nt][2*r+1] = p1;
                rsum += p0 + p1;
            }
            rsum += __shfl_xor_sync(0xffffffffu, rsum, 1);
            rsum += __shfl_xor_sync(0xffffffffu, rsum, 2);
            l_i[r] = l_i[r] * corr + rsum;
#pragma unroll
            for (int nt = 0; nt < 8; nt++) {
                accO[nt][2*r]   *= corr;
                accO[nt][2*r+1] *= corr;
            }
        }

        // stage P (tf32) to SMEM
#pragma unroll
        for (int nt = 0; nt < 8; nt++) {
            uint32_t* pr0 = Ps + (wr0 + g)*QP     + nt*8 + 2*t;
            uint32_t* pr1 = Ps + (wr0 + g + 8)*QP + nt*8 + 2*t;
            pr0[0] = f2tf32(accS[nt][0]); pr0[1] = f2tf32(accS[nt][1]);
            pr1[0] = f2tf32(accS[nt][2]); pr1[1] = f2tf32(accS[nt][3]);
        }
        __syncwarp();   // Ps tile rows are warp-private; no block sync needed

        // O += P @ V : warp computes 16x64
#pragma unroll
        for (int kc = 0; kc < 8; kc++) {
            uint32_t af[4];
            const uint32_t* pb = Ps + (wr0 + g)*QP + kc*8 + t;
            af[0] = pb[0]; af[1] = pb[8*QP]; af[2] = pb[4]; af[3] = pb[8*QP + 4];
#pragma unroll
            for (int nt = 0; nt < 8; nt++) {
                uint32_t bf[2];
                const uint32_t* vb = Vs + (kc*8 + t)*VP + nt*8 + g;
                bf[0] = vb[0]; bf[1] = vb[4*VP];
                mma_tf32(accO[nt], af, bf);
            }
        }
    }

    // normalize + write [b, s, h*dh]
    const float inv0 = 1.f / l_i[0];
    const float inv1 = 1.f / l_i[1];
    const int row0 = q0 + wr0 + g;
    float* outb = AO + ((size_t)bb*SEQ + row0)*DMODEL + hh*DHEAD;
#pragma unroll
    for (int nt = 0; nt < 8; nt++) {
        const int col = nt*8 + 2*t;
        *reinterpret_cast<float2*>(outb + col) =
            make_float2(accO[nt][0]*inv0, accO[nt][1]*inv0);
        *reinterpret_cast<float2*>(outb + 8*DMODEL + col) =
            make_float2(accO[nt][2]*inv1, accO[nt][3]*inv1);
    }
}

// ---------------------------------------------------------------------------
extern "C" void kernel_launch(void* const* d_in, const int* in_sizes, int n_in,
                              void* d_out, int out_size)
{
    const float* x    = (const float*)d_in[0];
    const float* Wq   = (const float*)d_in[1];
    const float* bq   = (const float*)d_in[2];
    const float* Wk   = (const float*)d_in[3];
    const float* bk   = (const float*)d_in[4];
    const float* Wv   = (const float*)d_in[5];
    const float* bv   = (const float*)d_in[6];
    const float* Wo   = (const float*)d_in[7];
    const float* bo   = (const float*)d_in[8];
    const int*   mask = (const int*)  d_in[9];
    float* out = (float*)d_out;

    float *Qp, *Kp, *Vp, *AOp;
    cudaGetSymbolAddress((void**)&Qp,  g_Q);
    cudaGetSymbolAddress((void**)&Kp,  g_K);
    cudaGetSymbolAddress((void**)&Vp,  g_V);
    cudaGetSymbolAddress((void**)&AOp, g_AO);

    const int smem_fa = FA_SMEM_WORDS * (int)sizeof(uint32_t);   // 70656
    cudaFuncSetAttribute(flash_attn_mma,
                         cudaFuncAttributeMaxDynamicSharedMemorySize, smem_fa);

    dim3 gg(DMODEL/128, MROWS/128);   // (8, 64)
    gemm_mma<1><<<gg, 256>>>(x, Wq, bq, Qp);
    gemm_mma<1><<<gg, 256>>>(x, Wk, bk, Kp);
    gemm_mma<1><<<gg, 256>>>(x, Wv, bv, Vp);

    dim3 gattn(SEQ/64, NHEAD, BATCH);  // (32, 16, 4)
    flash_attn_mma<<<gattn, 128, smem_fa>>>(Qp, Kp, Vp, AOp, mask);

    gemm_mma<0><<<gg, 256>>>(AOp, Wo, bo, out);
}

// round 5
// speedup vs baseline: 3.1190x; 1.0091x over previous
#include <cuda_runtime.h>
#include <math.h>
#include <stdint.h>

#define BATCH  4
#define SEQ    2048
#define DMODEL 1024
#define NHEAD  16
#define DHEAD  64
#define MROWS  (BATCH*SEQ)   // 8192

// Scratch (tf32-bit-pattern floats unless noted)
__device__ float g_Q [BATCH*NHEAD*SEQ*DHEAD];
__device__ float g_K [BATCH*NHEAD*SEQ*DHEAD];
__device__ float g_V [BATCH*NHEAD*SEQ*DHEAD];
__device__ float g_AO[(size_t)MROWS*DMODEL];
__device__ float g_X [(size_t)MROWS*DMODEL];       // x pre-rounded to tf32
__device__ float g_W4[4][(size_t)DMODEL*DMODEL];   // weights pre-rounded to tf32

// ---------------------------------------------------------------------------
__device__ __forceinline__ uint32_t f2tf32(float f) {
    uint32_t u;
    asm("cvt.rna.tf32.f32 %0, %1;" : "=r"(u) : "f"(f));
    return u;
}
__device__ __forceinline__ void mma_tf32(float* d, const uint32_t* a,
                                         const uint32_t* b) {
    asm volatile(
        "mma.sync.aligned.m16n8k8.row.col.f32.tf32.tf32.f32 "
        "{%0,%1,%2,%3}, {%4,%5,%6,%7}, {%8,%9}, {%0,%1,%2,%3};"
        : "+f"(d[0]), "+f"(d[1]), "+f"(d[2]), "+f"(d[3])
        : "r"(a[0]), "r"(a[1]), "r"(a[2]), "r"(a[3]),
          "r"(b[0]), "r"(b[1]));
}
__device__ __forceinline__ uint32_t smem_u32(const void* p) {
    uint32_t a;
    asm("{ .reg .u64 t; cvta.to.shared.u64 t, %1; cvt.u32.u64 %0, t; }" : "=r"(a) : "l"(p));
    return a;
}
__device__ __forceinline__ void cp_async16(uint32_t dst, const void* src) {
    asm volatile("cp.async.ca.shared.global [%0], [%1], 16;" :: "r"(dst), "l"(src));
}
__device__ __forceinline__ void cp_commit() {
    asm volatile("cp.async.commit_group;" ::: "memory");
}
template<int N>
__device__ __forceinline__ void cp_wait() {
    asm volatile("cp.async.wait_group %0;" :: "n"(N) : "memory");
}

// ---------------------------------------------------------------------------
// Elementwise fp32 -> tf32(rna) bit-pattern pass
// ---------------------------------------------------------------------------
__global__ void cvt_tf32_pass(const float* __restrict__ in,
                              float* __restrict__ outp, int n4) {
    const int i = blockIdx.x * blockDim.x + threadIdx.x;
    if (i < n4) {
        float4 v = *reinterpret_cast<const float4*>(in + (size_t)i * 4);
        uint4 u = { f2tf32(v.x), f2tf32(v.y), f2tf32(v.z), f2tf32(v.w) };
        *reinterpret_cast<uint4*>(outp + (size_t)i * 4) = u;
    }
}

// ---------------------------------------------------------------------------
// tf32 tensor-core GEMM, 3-stage cp.async pipeline.
// Inputs A, W already tf32-rounded. CTA 128x128, BK=16, 8 warps, 64x32/warp.
// CVTOUT=1: round (acc+bias) to tf32 before store (for Q/K/V scratch).
// ---------------------------------------------------------------------------
#define APITCH 20
#define BPITCH 136
#define GSTAGES 3
#define A_ST (128*APITCH)   // 2560 words
#define B_ST (16*BPITCH)    // 2176 words
#define GEMM_SMEM_BYTES (GSTAGES*(A_ST+B_ST)*4)   // 56832

template<int REMAP, int CVTOUT>
__global__ __launch_bounds__(256) void gemm_mma(
    const float* __restrict__ A, const float* __restrict__ W,
    const float* __restrict__ bias, float* __restrict__ C)
{
    extern __shared__ uint32_t su[];
    const uint32_t sbase = smem_u32(su);

    const int tid  = threadIdx.x;
    const int wid  = tid >> 5, lane = tid & 31;
    const int g    = lane >> 2, t = lane & 3;
    const int m0   = blockIdx.y * 128, n0 = blockIdx.x * 128;
    const int wm0  = (wid >> 2) * 64, wn0 = (wid & 3) * 32;

    const int am[2] = { tid >> 2, (tid + 256) >> 2 };
    const int ak[2] = { (tid & 3) << 2, ((tid + 256) & 3) << 2 };
    const int bk[2] = { tid >> 5, (tid + 256) >> 5 };
    const int bn[2] = { (tid & 31) << 2, ((tid + 256) & 31) << 2 };

    auto issue = [&](int kt, int s) {
        const uint32_t abase = sbase + (uint32_t)(s * A_ST) * 4;
        const uint32_t bbase = sbase + (uint32_t)(GSTAGES * A_ST + s * B_ST) * 4;
#pragma unroll
        for (int i = 0; i < 2; i++) {
            cp_async16(abase + (uint32_t)(am[i] * APITCH + ak[i]) * 4,
                       A + (size_t)(m0 + am[i]) * DMODEL + kt * 16 + ak[i]);
            cp_async16(bbase + (uint32_t)(bk[i] * BPITCH + bn[i]) * 4,
                       W + (size_t)(kt * 16 + bk[i]) * DMODEL + n0 + bn[i]);
        }
        cp_commit();
    };

    float acc[4][4][4];
#pragma unroll
    for (int mt = 0; mt < 4; mt++)
#pragma unroll
        for (int nt = 0; nt < 4; nt++)
#pragma unroll
            for (int r = 0; r < 4; r++) acc[mt][nt][r] = 0.f;

    issue(0, 0);
    issue(1, 1);

    const int NKT = DMODEL / 16;   // 64
    for (int kt = 0; kt < NKT; kt++) {
        const int s = kt % GSTAGES;
        if (kt + 1 < NKT) cp_wait<1>(); else cp_wait<0>();
        __syncthreads();
        if (kt + 2 < NKT) issue(kt + 2, (kt + 2) % GSTAGES);

        const uint32_t* As = su + s * A_ST;
        const uint32_t* Bs = su + GSTAGES * A_ST + s * B_ST;
#pragma unroll
        for (int ks = 0; ks < 2; ks++) {
            const int k0 = ks * 8;
            uint32_t af[4][4], bf[4][2];
#pragma unroll
            for (int mt = 0; mt < 4; mt++) {
                const int rb = wm0 + mt * 16;
                af[mt][0] = As[(rb + g)     * APITCH + k0 + t];
                af[mt][1] = As[(rb + g + 8) * APITCH + k0 + t];
                af[mt][2] = As[(rb + g)     * APITCH + k0 + t + 4];
                af[mt][3] = As[(rb + g + 8) * APITCH + k0 + t + 4];
            }
#pragma unroll
            for (int nt = 0; nt < 4; nt++) {
                const int col = wn0 + nt * 8 + g;
                bf[nt][0] = Bs[(k0 + t)     * BPITCH + col];
                bf[nt][1] = Bs[(k0 + t + 4) * BPITCH + col];
            }
#pragma unroll
            for (int mt = 0; mt < 4; mt++)
#pragma unroll
                for (int nt = 0; nt < 4; nt++)
                    mma_tf32(acc[mt][nt], af[mt], bf[nt]);
        }
    }

#pragma unroll
    for (int mt = 0; mt < 4; mt++) {
#pragma unroll
        for (int nt = 0; nt < 4; nt++) {
            const int row = m0 + wm0 + mt * 16 + g;
            const int col = n0 + wn0 + nt * 8 + t * 2;
            const float b0 = bias[col], b1 = bias[col + 1];
#pragma unroll
            for (int half = 0; half < 2; half++) {
                const int m = row + half * 8;
                float v0 = acc[mt][nt][half*2]   + b0;
                float v1 = acc[mt][nt][half*2+1] + b1;
                if (CVTOUT) {
                    v0 = __uint_as_float(f2tf32(v0));
                    v1 = __uint_as_float(f2tf32(v1));
                }
                float* outp;
                if (REMAP) {
                    const int bb = m >> 11, ss = m & 2047;
                    const int hh = col >> 6, dd = col & 63;
                    outp = C + (((size_t)(bb * NHEAD + hh) * SEQ + ss) * DHEAD + dd);
                } else {
                    outp = C + (size_t)m * DMODEL + col;
                }
                *reinterpret_cast<float2*>(outp) = make_float2(v0, v1);
            }
        }
    }
}

// ---------------------------------------------------------------------------
// Flash attention, tf32 mma.sync, cp.async double-buffered K/V.
// Inputs Q/K/V already tf32-rounded. Output AO written tf32-rounded.
// CTA 128 threads / 4 warps, q-tile 64, kv-tile 64.
// SMEM words: Q[64*68] | K[2][64*68] | V[2][64*72] | P[64*68]
// ---------------------------------------------------------------------------
#define QP 68
#define VP 72
#define FQ_OFF 0
#define FK_OFF 4352
#define FK_ST  4352
#define FV_OFF 13056
#define FV_ST  4608
#define FP_OFF 22272
#define FA_SMEM_BYTES ((FP_OFF + 4352) * 4)   // 106496

__global__ __launch_bounds__(128) void flash_attn_mma(
    const float* __restrict__ Q, const float* __restrict__ K,
    const float* __restrict__ V, float* __restrict__ AO,
    const int* __restrict__ maskp)
{
    extern __shared__ uint32_t su[];
    const uint32_t sbase = smem_u32(su);
    uint32_t* Qs = su + FQ_OFF;
    uint32_t* Ps = su + FP_OFF;

    const int tid = threadIdx.x;
    const int wid = tid >> 5, lane = tid & 31;
    const int g = lane >> 2, t = lane & 3;
    const int qt = blockIdx.x, hh = blockIdx.y, bb = blockIdx.z;
    const int q0 = qt * 64;
    const int wr0 = wid * 16;
    const size_t bh = ((size_t)bb*NHEAD + hh) * SEQ * DHEAD;
    const int causal = (maskp[0] != 0);
    const int ktmax = causal ? qt : (SEQ/64 - 1);

    // per-thread copy coords: chunk c = tid + i*128; row=c>>4, col4=(c&15)*4
    auto issue_kv = [&](int kt, int s) {
        const float* Kg = K + bh + (size_t)kt*64*DHEAD;
        const float* Vg = V + bh + (size_t)kt*64*DHEAD;
        const uint32_t kb = sbase + (uint32_t)(FK_OFF + s*FK_ST) * 4;
        const uint32_t vb = sbase + (uint32_t)(FV_OFF + s*FV_ST) * 4;
#pragma unroll
        for (int i = 0; i < 8; i++) {
            const int c = tid + i * 128;
            const int r = c >> 4, col = (c & 15) * 4;
            cp_async16(kb + (uint32_t)(r*QP + col) * 4, Kg + r*DHEAD + col);
            cp_async16(vb + (uint32_t)(r*VP + col) * 4, Vg + r*DHEAD + col);
        }
        cp_commit();
    };

    // Q tile + KV stage 0 as group 0
    {
        const float* Qg = Q + bh + (size_t)q0 * DHEAD;
        const uint32_t qb = sbase + (uint32_t)FQ_OFF * 4;
#pragma unroll
        for (int i = 0; i < 8; i++) {
            const int c = tid + i * 128;
            const int r = c >> 4, col = (c & 15) * 4;
            cp_async16(qb + (uint32_t)(r*QP + col) * 4, Qg + r*DHEAD + col);
        }
        const float* Kg = K + bh;
        const float* Vg = V + bh;
        const uint32_t kb = sbase + (uint32_t)FK_OFF * 4;
        const uint32_t vb = sbase + (uint32_t)FV_OFF * 4;
#pragma unroll
        for (int i = 0; i < 8; i++) {
            const int c = tid + i * 128;
            const int r = c >> 4, col = (c & 15) * 4;
            cp_async16(kb + (uint32_t)(r*QP + col) * 4, Kg + r*DHEAD + col);
            cp_async16(vb + (uint32_t)(r*VP + col) * 4, Vg + r*DHEAD + col);
        }
        cp_commit();
    }
    if (ktmax >= 1) issue_kv(1, 1);

    float m_i[2] = { -INFINITY, -INFINITY };
    float l_i[2] = { 0.f, 0.f };
    float accO[8][4];
#pragma unroll
    for (int nt = 0; nt < 8; nt++)
#pragma unroll
        for (int c = 0; c < 4; c++) accO[nt][c] = 0.f;

    for (int kt = 0; kt <= ktmax; kt++) {
        const int s = kt & 1;
        if (kt < ktmax) cp_wait<1>(); else cp_wait<0>();
        __syncthreads();

        const uint32_t* Ks = su + FK_OFF + s*FK_ST;
        const uint32_t* Vs = su + FV_OFF + s*FV_ST;

        // S = Q @ K^T (warp: 16x64)
        float accS[8][4];
#pragma unroll
        for (int nt = 0; nt < 8; nt++)
#pragma unroll
            for (int c = 0; c < 4; c++) accS[nt][c] = 0.f;
#pragma unroll
        for (int kc = 0; kc < 8; kc++) {
            uint32_t af[4];
            const uint32_t* qb = Qs + (wr0 + g)*QP + kc*8 + t;
            af[0] = qb[0]; af[1] = qb[8*QP]; af[2] = qb[4]; af[3] = qb[8*QP + 4];
#pragma unroll
            for (int nt = 0; nt < 8; nt++) {
                uint32_t bf[2];
                const uint32_t* kbp = Ks + (nt*8 + g)*QP + kc*8 + t;
                bf[0] = kbp[0]; bf[1] = kbp[4];
                mma_tf32(accS[nt], af, bf);
            }
        }

        const bool diag = causal && (kt == qt);
#pragma unroll
        for (int nt = 0; nt < 8; nt++)
#pragma unroll
            for (int c = 0; c < 4; c++) {
                float sv = accS[nt][c] * 0.125f;
                if (diag) {
                    const int grow = q0 + wr0 + g + ((c & 2) ? 8 : 0);
                    const int gcol = kt*64 + nt*8 + 2*t + (c & 1);
                    if (gcol > grow) sv = -INFINITY;
                }
                accS[nt][c] = sv;
            }

#pragma unroll
        for (int r = 0; r < 2; r++) {
            float rmax = -INFINITY;
#pragma unroll
            for (int nt = 0; nt < 8; nt++)
                rmax = fmaxf(rmax, fmaxf(accS[nt][2*r], accS[nt][2*r+1]));
            rmax = fmaxf(rmax, __shfl_xor_sync(0xffffffffu, rmax, 1));
            rmax = fmaxf(rmax, __shfl_xor_sync(0xffffffffu, rmax, 2));
            const float mnew = fmaxf(m_i[r], rmax);
            const float corr = __expf(m_i[r] - mnew);
            m_i[r] = mnew;
            float rsum = 0.f;
#pragma unroll
            for (int nt = 0; nt < 8; nt++) {
                const float p0 = __expf(accS[nt][2*r]   - mnew);
                const float p1 = __expf(accS[nt][2*r+1] - mnew);
                accS[nt][2*r] = p0; accS[nt][2*r+1] = p1;
                rsum += p0 + p1;
            }
            rsum += __shfl_xor_sync(0xffffffffu, rsum, 1);
            rsum += __shfl_xor_sync(0xffffffffu, rsum, 2);
            l_i[r] = l_i[r] * corr + rsum;
#pragma unroll
            for (int nt = 0; nt < 8; nt++) {
                accO[nt][2*r]   *= corr;
                accO[nt][2*r+1] *= corr;
            }
        }

        // stage P (tf32) into warp-private SMEM rows
#pragma unroll
        for (int nt = 0; nt < 8; nt++) {
            uint32_t* pr0 = Ps + (wr0 + g)*QP     + nt*8 + 2*t;
            uint32_t* pr1 = Ps + (wr0 + g + 8)*QP + nt*8 + 2*t;
            pr0[0] = f2tf32(accS[nt][0]); pr0[1] = f2tf32(accS[nt][1]);
            pr1[0] = f2tf32(accS[nt][2]); pr1[1] = f2tf32(accS[nt][3]);
        }
        __syncwarp();

        // O += P @ V
#pragma unroll
        for (int kc = 0; kc < 8; kc++) {
            uint32_t af[4];
            const uint32_t* pb = Ps + (wr0 + g)*QP + kc*8 + t;
            af[0] = pb[0]; af[1] = pb[8*QP]; af[2] = pb[4]; af[3] = pb[8*QP + 4];
#pragma unroll
            for (int nt = 0; nt < 8; nt++) {
                uint32_t bf[2];
                const uint32_t* vbp = Vs + (kc*8 + t)*VP + nt*8 + g;
                bf[0] = vbp[0]; bf[1] = vbp[4*VP];
                mma_tf32(accO[nt], af, bf);
            }
        }

        __syncthreads();   // everyone done reading K/V stage s
        if (kt + 2 <= ktmax) issue_kv(kt + 2, s);
    }

    // normalize + write AO (tf32-rounded, [b, s, h*dh])
    const float inv0 = 1.f / l_i[0];
    const float inv1 = 1.f / l_i[1];
    const int row0 = q0 + wr0 + g;
    float* outb = AO + ((size_t)bb*SEQ + row0)*DMODEL + hh*DHEAD;
#pragma unroll
    for (int nt = 0; nt < 8; nt++) {
        const int col = nt*8 + 2*t;
        float2 o0 = make_float2(__uint_as_float(f2tf32(accO[nt][0]*inv0)),
                                __uint_as_float(f2tf32(accO[nt][1]*inv0)));
        float2 o1 = make_float2(__uint_as_float(f2tf32(accO[nt][2]*inv1)),
                                __uint_as_float(f2tf32(accO[nt][3]*inv1)));
        *reinterpret_cast<float2*>(outb + col) = o0;
        *reinterpret_cast<float2*>(outb + 8*DMODEL + col) = o1;
    }
}

// ---------------------------------------------------------------------------
extern "C" void kernel_launch(void* const* d_in, const int* in_sizes, int n_in,
                              void* d_out, int out_size)
{
    const float* x    = (const float*)d_in[0];
    const float* Wq   = (const float*)d_in[1];
    const float* bq   = (const float*)d_in[2];
    const float* Wk   = (const float*)d_in[3];
    const float* bk   = (const float*)d_in[4];
    const float* Wv   = (const float*)d_in[5];
    const float* bv   = (const float*)d_in[6];
    const float* Wo   = (const float*)d_in[7];
    const float* bo   = (const float*)d_in[8];
    const int*   mask = (const int*)  d_in[9];
    float* out = (float*)d_out;

    float *Qp, *Kp, *Vp, *AOp, *Xp, *Wp;
    cudaGetSymbolAddress((void**)&Qp,  g_Q);
    cudaGetSymbolAddress((void**)&Kp,  g_K);
    cudaGetSymbolAddress((void**)&Vp,  g_V);
    cudaGetSymbolAddress((void**)&AOp, g_AO);
    cudaGetSymbolAddress((void**)&Xp,  g_X);
    cudaGetSymbolAddress((void**)&Wp,  g_W4);
    float* WqT = Wp + 0 * (size_t)DMODEL*DMODEL;
    float* WkT = Wp + 1 * (size_t)DMODEL*DMODEL;
    float* WvT = Wp + 2 * (size_t)DMODEL*DMODEL;
    float* WoT = Wp + 3 * (size_t)DMODEL*DMODEL;

    cudaFuncSetAttribute(gemm_mma<1,1>, cudaFuncAttributeMaxDynamicSharedMemorySize, GEMM_SMEM_BYTES);
    cudaFuncSetAttribute(gemm_mma<0,0>, cudaFuncAttributeMaxDynamicSharedMemorySize, GEMM_SMEM_BYTES);
    cudaFuncSetAttribute(flash_attn_mma, cudaFuncAttributeMaxDynamicSharedMemorySize, FA_SMEM_BYTES);

    // pre-round inputs to tf32
    const int nx4 = MROWS * DMODEL / 4;      // 2,097,152
    const int nw4 = DMODEL * DMODEL / 4;     //   262,144
    cvt_tf32_pass<<<(nx4 + 255)/256, 256>>>(x,  Xp,  nx4);
    cvt_tf32_pass<<<(nw4 + 255)/256, 256>>>(Wq, WqT, nw4);
    cvt_tf32_pass<<<(nw4 + 255)/256, 256>>>(Wk, WkT, nw4);
    cvt_tf32_pass<<<(nw4 + 255)/256, 256>>>(Wv, WvT, nw4);
    cvt_tf32_pass<<<(nw4 + 255)/256, 256>>>(Wo, WoT, nw4);

    dim3 gg(DMODEL/128, MROWS/128);   // (8, 64)
    gemm_mma<1,1><<<gg, 256, GEMM_SMEM_BYTES>>>(Xp, WqT, bq, Qp);
    gemm_mma<1,1><<<gg, 256, GEMM_SMEM_BYTES>>>(Xp, WkT, bk, Kp);
    gemm_mma<1,1><<<gg, 256, GEMM_SMEM_BYTES>>>(Xp, WvT, bv, Vp);

    dim3 gattn(SEQ/64, NHEAD, BATCH);  // (32, 16, 4)
    flash_attn_mma<<<gattn, 128, FA_SMEM_BYTES>>>(Qp, Kp, Vp, AOp, mask);

    gemm_mma<0,0><<<gg, 256, GEMM_SMEM_BYTES>>>(AOp, WoT, bo, out);
}

// round 6
// speedup vs baseline: 3.5206x; 1.1288x over previous
#include <cuda_runtime.h>
#include <math.h>
#include <stdint.h>

#define BATCH  4
#define SEQ    2048
#define DMODEL 1024
#define NHEAD  16
#define DHEAD  64
#define MROWS  (BATCH*SEQ)   // 8192

// Scratch (tf32-bit-pattern floats)
__device__ float g_Q [BATCH*NHEAD*SEQ*DHEAD];
__device__ float g_K [BATCH*NHEAD*SEQ*DHEAD];
__device__ float g_V [BATCH*NHEAD*SEQ*DHEAD];
__device__ float g_AO[(size_t)MROWS*DMODEL];
__device__ float g_X [(size_t)MROWS*DMODEL];
__device__ float g_W4[4][(size_t)DMODEL*DMODEL];

// ---------------------------------------------------------------------------
__device__ __forceinline__ uint32_t f2tf32(float f) {
    uint32_t u;
    asm("cvt.rna.tf32.f32 %0, %1;" : "=r"(u) : "f"(f));
    return u;
}
__device__ __forceinline__ void mma_tf32(float* d, const uint32_t* a,
                                         uint32_t b0, uint32_t b1) {
    asm volatile(
        "mma.sync.aligned.m16n8k8.row.col.f32.tf32.tf32.f32 "
        "{%0,%1,%2,%3}, {%4,%5,%6,%7}, {%8,%9}, {%0,%1,%2,%3};"
        : "+f"(d[0]), "+f"(d[1]), "+f"(d[2]), "+f"(d[3])
        : "r"(a[0]), "r"(a[1]), "r"(a[2]), "r"(a[3]),
          "r"(b0), "r"(b1));
}
__device__ __forceinline__ void ldsm_x4(uint32_t* r, uint32_t addr) {
    asm volatile("ldmatrix.sync.aligned.m8n8.x4.shared.b16 {%0,%1,%2,%3}, [%4];"
        : "=r"(r[0]), "=r"(r[1]), "=r"(r[2]), "=r"(r[3]) : "r"(addr));
}
__device__ __forceinline__ uint32_t smem_u32(const void* p) {
    uint32_t a;
    asm("{ .reg .u64 t; cvta.to.shared.u64 t, %1; cvt.u32.u64 %0, t; }" : "=r"(a) : "l"(p));
    return a;
}
__device__ __forceinline__ void cp_async16(uint32_t dst, const void* src) {
    asm volatile("cp.async.ca.shared.global [%0], [%1], 16;" :: "r"(dst), "l"(src));
}
__device__ __forceinline__ void cp_commit() {
    asm volatile("cp.async.commit_group;" ::: "memory");
}
template<int N>
__device__ __forceinline__ void cp_wait() {
    asm volatile("cp.async.wait_group %0;" :: "n"(N) : "memory");
}

// ---------------------------------------------------------------------------
__global__ void cvt_tf32_pass(const float* __restrict__ in,
                              float* __restrict__ outp, int n4) {
    const int i = blockIdx.x * blockDim.x + threadIdx.x;
    if (i < n4) {
        float4 v = *reinterpret_cast<const float4*>(in + (size_t)i * 4);
        uint4 u = { f2tf32(v.x), f2tf32(v.y), f2tf32(v.z), f2tf32(v.w) };
        *reinterpret_cast<uint4*>(outp + (size_t)i * 4) = u;
    }
}

// ---------------------------------------------------------------------------
// tf32 GEMM, 3-stage cp.async, A-frags via ldmatrix.
// ---------------------------------------------------------------------------
#define APITCH 20
#define BPITCH 136
#define GSTAGES 3
#define A_ST (128*APITCH)
#define B_ST (16*BPITCH)
#define GEMM_SMEM_BYTES (GSTAGES*(A_ST+B_ST)*4)   // 56832

template<int REMAP, int CVTOUT>
__global__ __launch_bounds__(256) void gemm_mma(
    const float* __restrict__ A, const float* __restrict__ W,
    const float* __restrict__ bias, float* __restrict__ C)
{
    extern __shared__ uint32_t su[];
    const uint32_t sbase = smem_u32(su);

    const int tid  = threadIdx.x;
    const int wid  = tid >> 5, lane = tid & 31;
    const int g    = lane >> 2, t = lane & 3;
    const int m0   = blockIdx.y * 128, n0 = blockIdx.x * 128;
    const int wm0  = (wid >> 2) * 64, wn0 = (wid & 3) * 32;

    // ldmatrix per-lane source row/col for A fragments
    const int arow_l = (lane & 7) + ((lane >> 3) & 1) * 8;
    const int acol_l = (lane >> 4) * 4;
    uint32_t aoff[4];
#pragma unroll
    for (int mt = 0; mt < 4; mt++)
        aoff[mt] = (uint32_t)(((wm0 + mt * 16 + arow_l) * APITCH + acol_l) * 4);

    const int am[2] = { tid >> 2, (tid + 256) >> 2 };
    const int ak[2] = { (tid & 3) << 2, ((tid + 256) & 3) << 2 };
    const int bk[2] = { tid >> 5, (tid + 256) >> 5 };
    const int bn[2] = { (tid & 31) << 2, ((tid + 256) & 31) << 2 };

    auto issue = [&](int kt, int s) {
        const uint32_t abase = sbase + (uint32_t)(s * A_ST) * 4;
        const uint32_t bbase = sbase + (uint32_t)(GSTAGES * A_ST + s * B_ST) * 4;
#pragma unroll
        for (int i = 0; i < 2; i++) {
            cp_async16(abase + (uint32_t)(am[i] * APITCH + ak[i]) * 4,
                       A + (size_t)(m0 + am[i]) * DMODEL + kt * 16 + ak[i]);
            cp_async16(bbase + (uint32_t)(bk[i] * BPITCH + bn[i]) * 4,
                       W + (size_t)(kt * 16 + bk[i]) * DMODEL + n0 + bn[i]);
        }
        cp_commit();
    };

    float acc[4][4][4];
#pragma unroll
    for (int mt = 0; mt < 4; mt++)
#pragma unroll
        for (int nt = 0; nt < 4; nt++)
#pragma unroll
            for (int r = 0; r < 4; r++) acc[mt][nt][r] = 0.f;

    issue(0, 0);
    issue(1, 1);

    const int NKT = DMODEL / 16;   // 64
    for (int kt = 0; kt < NKT; kt++) {
        const int s = kt % GSTAGES;
        if (kt + 1 < NKT) cp_wait<1>(); else cp_wait<0>();
        __syncthreads();
        if (kt + 2 < NKT) issue(kt + 2, (kt + 2) % GSTAGES);

        const uint32_t abase = sbase + (uint32_t)(s * A_ST) * 4;
        const uint32_t* Bs = su + GSTAGES * A_ST + s * B_ST;
#pragma unroll
        for (int ks = 0; ks < 2; ks++) {
            const int k0 = ks * 8;
            uint32_t af[4][4];
#pragma unroll
            for (int mt = 0; mt < 4; mt++)
                ldsm_x4(af[mt], abase + aoff[mt] + (uint32_t)(k0 * 4));
            uint32_t bf[4][2];
#pragma unroll
            for (int nt = 0; nt < 4; nt++) {
                const int col = wn0 + nt * 8 + g;
                bf[nt][0] = Bs[(k0 + t)     * BPITCH + col];
                bf[nt][1] = Bs[(k0 + t + 4) * BPITCH + col];
            }
#pragma unroll
            for (int mt = 0; mt < 4; mt++)
#pragma unroll
                for (int nt = 0; nt < 4; nt++)
                    mma_tf32(acc[mt][nt], af[mt], bf[nt][0], bf[nt][1]);
        }
    }

#pragma unroll
    for (int mt = 0; mt < 4; mt++) {
#pragma unroll
        for (int nt = 0; nt < 4; nt++) {
            const int row = m0 + wm0 + mt * 16 + g;
            const int col = n0 + wn0 + nt * 8 + t * 2;
            const float b0 = bias[col], b1 = bias[col + 1];
#pragma unroll
            for (int half = 0; half < 2; half++) {
                const int m = row + half * 8;
                float v0 = acc[mt][nt][half*2]   + b0;
                float v1 = acc[mt][nt][half*2+1] + b1;
                if (CVTOUT) {
                    v0 = __uint_as_float(f2tf32(v0));
                    v1 = __uint_as_float(f2tf32(v1));
                }
                float* outp;
                if (REMAP) {
                    const int bb = m >> 11, ss = m & 2047;
                    const int hh = col >> 6, dd = col & 63;
                    outp = C + (((size_t)(bb * NHEAD + hh) * SEQ + ss) * DHEAD + dd);
                } else {
                    outp = C + (size_t)m * DMODEL + col;
                }
                *reinterpret_cast<float2*>(outp) = make_float2(v0, v1);
            }
        }
    }
}

// ---------------------------------------------------------------------------
// Flash attention, tf32 mma.sync; Q/K/P frags via ldmatrix, V via LDS.
// ---------------------------------------------------------------------------
#define QP 68
#define VP 72
#define FQ_OFF 0
#define FK_OFF 4352
#define FK_ST  4352
#define FV_OFF 13056
#define FV_ST  4608
#define FP_OFF 22272
#define FA_SMEM_BYTES ((FP_OFF + 4352) * 4)   // 106496

__global__ __launch_bounds__(128) void flash_attn_mma(
    const float* __restrict__ Q, const float* __restrict__ K,
    const float* __restrict__ V, float* __restrict__ AO,
    const int* __restrict__ maskp)
{
    extern __shared__ uint32_t su[];
    const uint32_t sbase = smem_u32(su);
    uint32_t* Ps = su + FP_OFF;

    const int tid = threadIdx.x;
    const int wid = tid >> 5, lane = tid & 31;
    const int g = lane >> 2, t = lane & 3;
    const int qt = blockIdx.x, hh = blockIdx.y, bb = blockIdx.z;
    const int q0 = qt * 64;
    const int wr0 = wid * 16;
    const size_t bh = ((size_t)bb*NHEAD + hh) * SEQ * DHEAD;
    const int causal = (maskp[0] != 0);
    const int ktmax = causal ? qt : (SEQ/64 - 1);

    // ldmatrix per-lane offsets
    const int arow_l = (lane & 7) + ((lane >> 3) & 1) * 8;   // A-frag row within 16
    const int acol_l = (lane >> 4) * 4;                       // A-frag col half
    const uint32_t qoff = (uint32_t)(((wr0 + arow_l) * QP + acol_l) * 4);
    // K-frag (nt-pair): row within 16 = (lane>>4)*8 + (lane&7); col half = ((lane>>3)&1)*4
    const uint32_t koff = (uint32_t)((((lane >> 4) * 8 + (lane & 7)) * QP
                                      + ((lane >> 3) & 1) * 4) * 4);

    auto issue_kv = [&](int kt, int s) {
        const float* Kg = K + bh + (size_t)kt*64*DHEAD;
        const float* Vg = V + bh + (size_t)kt*64*DHEAD;
        const uint32_t kb = sbase + (uint32_t)(FK_OFF + s*FK_ST) * 4;
        const uint32_t vb = sbase + (uint32_t)(FV_OFF + s*FV_ST) * 4;
#pragma unroll
        for (int i = 0; i < 8; i++) {
            const int c = tid + i * 128;
            const int r = c >> 4, col = (c & 15) * 4;
            cp_async16(kb + (uint32_t)(r*QP + col) * 4, Kg + r*DHEAD + col);
            cp_async16(vb + (uint32_t)(r*VP + col) * 4, Vg + r*DHEAD + col);
        }
        cp_commit();
    };

    {   // Q tile + KV stage 0 as group 0
        const float* Qg = Q + bh + (size_t)q0 * DHEAD;
#pragma unroll
        for (int i = 0; i < 8; i++) {
            const int c = tid + i * 128;
            const int r = c >> 4, col = (c & 15) * 4;
            cp_async16(sbase + (uint32_t)(r*QP + col) * 4, Qg + r*DHEAD + col);
        }
        const float* Kg = K + bh;
        const float* Vg = V + bh;
        const uint32_t kb = sbase + (uint32_t)FK_OFF * 4;
        const uint32_t vb = sbase + (uint32_t)FV_OFF * 4;
#pragma unroll
        for (int i = 0; i < 8; i++) {
            const int c = tid + i * 128;
            const int r = c >> 4, col = (c & 15) * 4;
            cp_async16(kb + (uint32_t)(r*QP + col) * 4, Kg + r*DHEAD + col);
            cp_async16(vb + (uint32_t)(r*VP + col) * 4, Vg + r*DHEAD + col);
        }
        cp_commit();
    }
    if (ktmax >= 1) issue_kv(1, 1);

    float m_i[2] = { -INFINITY, -INFINITY };
    float l_i[2] = { 0.f, 0.f };
    float accO[8][4];
#pragma unroll
    for (int nt = 0; nt < 8; nt++)
#pragma unroll
        for (int c = 0; c < 4; c++) accO[nt][c] = 0.f;

    for (int kt = 0; kt <= ktmax; kt++) {
        const int s = kt & 1;
        if (kt < ktmax) cp_wait<1>(); else cp_wait<0>();
        __syncthreads();

        const uint32_t kbase = sbase + (uint32_t)(FK_OFF + s*FK_ST) * 4;
        const uint32_t* Vs = su + FV_OFF + s*FV_ST;

        // S = Q @ K^T (warp: 16x64)
        float accS[8][4];
#pragma unroll
        for (int nt = 0; nt < 8; nt++)
#pragma unroll
            for (int c = 0; c < 4; c++) accS[nt][c] = 0.f;
#pragma unroll
        for (int kc = 0; kc < 8; kc++) {
            uint32_t af[4];
            ldsm_x4(af, sbase + qoff + (uint32_t)(kc * 32));
#pragma unroll
            for (int ntp = 0; ntp < 4; ntp++) {
                uint32_t kr[4];
                ldsm_x4(kr, kbase + (uint32_t)(ntp * 16 * QP * 4) + koff
                            + (uint32_t)(kc * 32));
                mma_tf32(accS[2*ntp],   af, kr[0], kr[1]);
                mma_tf32(accS[2*ntp+1], af, kr[2], kr[3]);
            }
        }

        const bool diag = causal && (kt == qt);
#pragma unroll
        for (int nt = 0; nt < 8; nt++)
#pragma unroll
            for (int c = 0; c < 4; c++) {
                float sv = accS[nt][c] * 0.125f;
                if (diag) {
                    const int grow = q0 + wr0 + g + ((c & 2) ? 8 : 0);
                    const int gcol = kt*64 + nt*8 + 2*t + (c & 1);
                    if (gcol > grow) sv = -INFINITY;
                }
                accS[nt][c] = sv;
            }

#pragma unroll
        for (int r = 0; r < 2; r++) {
            float rmax = -INFINITY;
#pragma unroll
            for (int nt = 0; nt < 8; nt++)
                rmax = fmaxf(rmax, fmaxf(accS[nt][2*r], accS[nt][2*r+1]));
            rmax = fmaxf(rmax, __shfl_xor_sync(0xffffffffu, rmax, 1));
            rmax = fmaxf(rmax, __shfl_xor_sync(0xffffffffu, rmax, 2));
            const float mnew = fmaxf(m_i[r], rmax);
            const float corr = __expf(m_i[r] - mnew);
            m_i[r] = mnew;
            float rsum = 0.f;
#pragma unroll
            for (int nt = 0; nt < 8; nt++) {
                const float p0 = __expf(accS[nt][2*r]   - mnew);
                const float p1 = __expf(accS[nt][2*r+1] - mnew);
                accS[nt][2*r] = p0; accS[nt][2*r+1] = p1;
                rsum += p0 + p1;
            }
            rsum += __shfl_xor_sync(0xffffffffu, rsum, 1);
            rsum += __shfl_xor_sync(0xffffffffu, rsum, 2);
            l_i[r] = l_i[r] * corr + rsum;
#pragma unroll
            for (int nt = 0; nt < 8; nt++) {
                accO[nt][2*r]   *= corr;
                accO[nt][2*r+1] *= corr;
            }
        }

        // stage P (tf32) into warp-private SMEM rows
#pragma unroll
        for (int nt = 0; nt < 8; nt++) {
            uint32_t* pr0 = Ps + (wr0 + g)*QP     + nt*8 + 2*t;
            uint32_t* pr1 = Ps + (wr0 + g + 8)*QP + nt*8 + 2*t;
            pr0[0] = f2tf32(accS[nt][0]); pr0[1] = f2tf32(accS[nt][1]);
            pr1[0] = f2tf32(accS[nt][2]); pr1[1] = f2tf32(accS[nt][3]);
        }
        __syncwarp();

        // O += P @ V
        const uint32_t pbase = sbase + (uint32_t)FP_OFF * 4;
#pragma unroll
        for (int kc = 0; kc < 8; kc++) {
            uint32_t af[4];
            ldsm_x4(af, pbase + qoff + (uint32_t)(kc * 32));
#pragma unroll
            for (int nt = 0; nt < 8; nt++) {
                const uint32_t* vbp = Vs + (kc*8 + t)*VP + nt*8 + g;
                mma_tf32(accO[nt], af, vbp[0], vbp[4*VP]);
            }
        }

        __syncthreads();
        if (kt + 2 <= ktmax) issue_kv(kt + 2, s);
    }

    const float inv0 = 1.f / l_i[0];
    const float inv1 = 1.f / l_i[1];
    const int row0 = q0 + wr0 + g;
    float* outb = AO + ((size_t)bb*SEQ + row0)*DMODEL + hh*DHEAD;
#pragma unroll
    for (int nt = 0; nt < 8; nt++) {
        const int col = nt*8 + 2*t;
        float2 o0 = make_float2(__uint_as_float(f2tf32(accO[nt][0]*inv0)),
                                __uint_as_float(f2tf32(accO[nt][1]*inv0)));
        float2 o1 = make_float2(__uint_as_float(f2tf32(accO[nt][2]*inv1)),
                                __uint_as_float(f2tf32(accO[nt][3]*inv1)));
        *reinterpret_cast<float2*>(outb + col) = o0;
        *reinterpret_cast<float2*>(outb + 8*DMODEL + col) = o1;
    }
}

// ---------------------------------------------------------------------------
extern "C" void kernel_launch(void* const* d_in, const int* in_sizes, int n_in,
                              void* d_out, int out_size)
{
    const float* x    = (const float*)d_in[0];
    const float* Wq   = (const float*)d_in[1];
    const float* bq   = (const float*)d_in[2];
    const float* Wk   = (const float*)d_in[3];
    const float* bk   = (const float*)d_in[4];
    const float* Wv   = (const float*)d_in[5];
    const float* bv   = (const float*)d_in[6];
    const float* Wo   = (const float*)d_in[7];
    const float* bo   = (const float*)d_in[8];
    const int*   mask = (const int*)  d_in[9];
    float* out = (float*)d_out;

    float *Qp, *Kp, *Vp, *AOp, *Xp, *Wp;
    cudaGetSymbolAddress((void**)&Qp,  g_Q);
    cudaGetSymbolAddress((void**)&Kp,  g_K);
    cudaGetSymbolAddress((void**)&Vp,  g_V);
    cudaGetSymbolAddress((void**)&AOp, g_AO);
    cudaGetSymbolAddress((void**)&Xp,  g_X);
    cudaGetSymbolAddress((void**)&Wp,  g_W4);
    float* WqT = Wp + 0 * (size_t)DMODEL*DMODEL;
    float* WkT = Wp + 1 * (size_t)DMODEL*DMODEL;
    float* WvT = Wp + 2 * (size_t)DMODEL*DMODEL;
    float* WoT = Wp + 3 * (size_t)DMODEL*DMODEL;

    cudaFuncSetAttribute(gemm_mma<1,1>, cudaFuncAttributeMaxDynamicSharedMemorySize, GEMM_SMEM_BYTES);
    cudaFuncSetAttribute(gemm_mma<0,0>, cudaFuncAttributeMaxDynamicSharedMemorySize, GEMM_SMEM_BYTES);
    cudaFuncSetAttribute(flash_attn_mma, cudaFuncAttributeMaxDynamicSharedMemorySize, FA_SMEM_BYTES);

    const int nx4 = MROWS * DMODEL / 4;
    const int nw4 = DMODEL * DMODEL / 4;
    cvt_tf32_pass<<<(nx4 + 255)/256, 256>>>(x,  Xp,  nx4);
    cvt_tf32_pass<<<(nw4 + 255)/256, 256>>>(Wq, WqT, nw4);
    cvt_tf32_pass<<<(nw4 + 255)/256, 256>>>(Wk, WkT, nw4);
    cvt_tf32_pass<<<(nw4 + 255)/256, 256>>>(Wv, WvT, nw4);
    cvt_tf32_pass<<<(nw4 + 255)/256, 256>>>(Wo, WoT, nw4);

    dim3 gg(DMODEL/128, MROWS/128);   // (8, 64)
    gemm_mma<1,1><<<gg, 256, GEMM_SMEM_BYTES>>>(Xp, WqT, bq, Qp);
    gemm_mma<1,1><<<gg, 256, GEMM_SMEM_BYTES>>>(Xp, WkT, bk, Kp);
    gemm_mma<1,1><<<gg, 256, GEMM_SMEM_BYTES>>>(Xp, WvT, bv, Vp);

    dim3 gattn(SEQ/64, NHEAD, BATCH);  // (32, 16, 4)
    flash_attn_mma<<<gattn, 128, FA_SMEM_BYTES>>>(Qp, Kp, Vp, AOp, mask);

    gemm_mma<0,0><<<gg, 256, GEMM_SMEM_BYTES>>>(AOp, WoT, bo, out);
}